// round 7
// baseline (speedup 1.0000x reference)
#include <cuda_runtime.h>
#include <math.h>

// x (2,16,256,256) f32, conv_w (32,16,4,4), conv_b (32) -> out (2,32,256,256) f32.
// Ring of 40 offsets (radius 5), stable-select 16 smallest sigmoid-sims,
// rank-indexed 32x(16*16) mat-vec per pixel.
// Phase 2 uses: out = bias + sum_c wsum[c,o]*xc[c] - sum_{r,c} w[r,c,o]*xr[r,c],
// with channel-paired f32x2 accumulation: the float2 halo load (x_{2c2},x_{2c2+1})
// is used directly as the fma.f32x2 multiplier against channel-interleaved
// (negated) weight pairs; horizontal add in the epilogue.

#define B_      2
#define CCH     16
#define NC2     (CCH/2)        // 8 float2 channel-pairs
#define HH      256
#define WWIDTH  256
#define HW      (HH*WWIDTH)
#define OUTC    32
#define NOFF    40
#define NSEL    16

#define TW 32
#define TH 8
#define NTHR (TW*TH)           // 256
#define SW 42                  // TW + 2*5
#define SH 18                  // TH + 2*5
#define CPLANE (SW*SH)         // 756
#define XS_FLOATS (CPLANE*CCH)        // 12096 floats (= CPLANE*NC2 float2)
#define WS_FLOATS (NSEL*CCH*OUTC)     // 8192 (as [r][c2][o][2] float pairs)
#define WSUM_FLOATS (CCH*OUTC)        // 512  (as [c2][o][2] float pairs)
#define CB_FLOATS 32
#define SEL_WORDS (NSEL*NTHR)         // 4096
#define SMEM_BYTES ((XS_FLOATS + WS_FLOATS + WSUM_FLOATS + CB_FLOATS + SEL_WORDS)*4)

// Ring offsets, order matching _prf_offsets:
//  j 0..10 : dx=-5,   dy=j-5
//  j 11..19: dx=j-15, dy=+5
//  j 20..30: dx=+5,   dy=j-25
//  j 31..39: dx=j-35, dy=-5
__host__ __device__ constexpr int dxOf(int j){ return j<11 ? -5 : (j<20 ? j-15 : (j<31 ? 5 : j-35)); }
__host__ __device__ constexpr int dyOf(int j){ return j<11 ? j-5 : (j<20 ? 5 : (j<31 ? j-25 : -5)); }
__host__ __device__ constexpr int offOf(int j){ return dxOf(j)*SW + dyOf(j); }

typedef unsigned long long u64;

__device__ __forceinline__ void fma2(u64 &acc, u64 a, u64 b){
    asm("fma.rn.f32x2 %0, %1, %2, %0;" : "+l"(acc) : "l"(a), "l"(b));
}
__device__ __forceinline__ float2 unpack2(u64 v){
    float2 f;
    asm("mov.b64 {%0,%1}, %2;" : "=f"(f.x), "=f"(f.y) : "l"(v));
    return f;
}

__global__ __launch_bounds__(NTHR, 2)
void pkc2d_kernel(const float* __restrict__ x,
                  const float* __restrict__ cw,
                  const float* __restrict__ cb,
                  float* __restrict__ out)
{
    extern __shared__ float sm[];
    float2*   xs2  = reinterpret_cast<float2*>(sm);  // [c2][sy][sx] 8 x 18 x 42 float2
    float*    ws   = sm + XS_FLOATS;                 // [r][c2][o] float2-pairs (NEGATED)
    float*    wsum = ws + WS_FLOATS;                 // [c2][o] float2-pairs (positive)
    float*    cbs  = wsum + WSUM_FLOATS;             // [32]
    unsigned* selp = (unsigned*)(cbs + CB_FLOATS);   // [r][tid] 16 x 256

    const u64* xs2u  = reinterpret_cast<const u64*>(sm);
    const u64* wsumu = reinterpret_cast<const u64*>(wsum);

    const int tx = threadIdx.x, ty = threadIdx.y;
    const int tid = ty*TW + tx;
    const int gx0 = blockIdx.x*TW, gy0 = blockIdx.y*TH;
    const int bz  = blockIdx.z;

    const float* xb = x + (size_t)bz * CCH * HW;

    // ---- cooperative loads: halo tile as channel-paired float2 ----
    for (int i = tid; i < CPLANE*NC2; i += NTHR) {
        int c2  = i / CPLANE;
        int rem = i - c2*CPLANE;
        int sy  = rem / SW;
        int sx  = rem - sy*SW;
        int gy  = gy0 + sy - 5;
        int gxp = gx0 + sx - 5;
        float2 v = make_float2(0.f, 0.f);
        if ((unsigned)gy < (unsigned)HH && (unsigned)gxp < (unsigned)WWIDTH) {
            const float* p = xb + (2*c2)*HW + gy*WWIDTH + gxp;
            v.x = p[0];
            v.y = p[HW];
        }
        xs2[i] = v;
    }
    // ws: float index i = ((r*8 + c2)*32 + o)*2 + h, value = -cw[o*256 + (2c2+h)*16 + r]
    for (int i = tid; i < WS_FLOATS; i += NTHR) {
        int h  = i & 1;
        int o  = (i >> 1) & 31;
        int c2 = (i >> 6) & 7;
        int r  = i >> 9;
        ws[i] = -cw[o*256 + (2*c2 + h)*16 + r];
    }
    // wsum: float index j = (c2*32 + o)*2 + h, value = sum_r cw[o*256 + (2c2+h)*16 + r]
    for (int j = tid; j < WSUM_FLOATS; j += NTHR) {
        int h  = j & 1;
        int o  = (j >> 1) & 31;
        int c2 = j >> 6;
        const float4* p = reinterpret_cast<const float4*>(cw + o*256 + (2*c2 + h)*16);
        float4 a = p[0], b = p[1], c = p[2], d = p[3];
        wsum[j] = ((a.x+a.y)+(a.z+a.w)) + ((b.x+b.y)+(b.z+b.w))
                + ((c.x+c.y)+(c.z+c.w)) + ((d.x+d.y)+(d.z+d.w));
    }
    if (tid < 32) cbs[tid] = cb[tid];
    __syncthreads();

    // ================= Phase 1: per-own-pixel selection (bit-exact, unchanged) ====
    {
        const int base = (ty+5)*SW + (tx+5);

        float2 xc[NC2];
        #pragma unroll
        for (int c2 = 0; c2 < NC2; ++c2) xc[c2] = xs2[c2*CPLANE + base];

        // sims: sequential channel-order mul+add (matches reference reduction),
        // then sigmoid — REQUIRED: its fp32 rounding creates ties that the
        // stable argsort resolves by index (verified R5: removing it fails).
        float sims[NOFF];
        #pragma unroll
        for (int j = 0; j < NOFF; ++j) {
            const int off = offOf(j);
            float s = 0.f;
            #pragma unroll
            for (int c2 = 0; c2 < NC2; ++c2) {
                const float2 v = xs2[c2*CPLANE + base + off];
                s = __fadd_rn(s, __fmul_rn(v.x, xc[c2].x));
                s = __fadd_rn(s, __fmul_rn(v.y, xc[c2].y));
            }
            s *= 0.0625f;
            sims[j] = 1.0f / (1.0f + expf(-s));
        }

        // Stable argsort rank, one compare per unordered pair.
        int rk[NOFF];
        #pragma unroll
        for (int i = 0; i < NOFF; ++i) rk[i] = NOFF - 1 - i;
        #pragma unroll
        for (int i = 0; i < NOFF; ++i) {
            #pragma unroll
            for (int j = i+1; j < NOFF; ++j) {
                if (sims[i] <= sims[j]) { rk[j] += 1; rk[i] -= 1; }
            }
        }
        #pragma unroll
        for (int j = 0; j < NOFF; ++j) {
            if (rk[j] < NSEL)
                selp[rk[j]*NTHR + tid] = (unsigned)(offOf(j) + 512);
        }
    }
    __syncthreads();

    // ================= Phase 2: pixel-pair / half-OUTC mat-vec =================
    // thread t: ph = t>>7 -> o in [16*ph, 16*ph+16); pixels p0 = t&127 (rows 0..3)
    // and p1 = p0+128 (rows 4..7). Channel-paired accumulators:
    //   acc[pix][o] = (even-channel partial, odd-channel partial)
    const int pp = tid & 127;
    const int ph = tid >> 7;
    const int px = pp & 31;
    const int py = pp >> 5;

    const int b0 = (py+5)*SW + (px+5);
    const int b1 = b0 + 4*SW;

    u64 accA[16], accB[16];
    #pragma unroll
    for (int o = 0; o < 16; ++o) { accA[o] = 0ull; accB[o] = 0ull; }

    // ---- prepass: acc += wsum[c2][o] (.) xc-pair ----
    #pragma unroll
    for (int c2 = 0; c2 < NC2; ++c2) {
        const u64 x0 = xs2u[c2*CPLANE + b0];
        const u64 x1 = xs2u[c2*CPLANE + b1];
        const ulonglong2* wq =
            reinterpret_cast<const ulonglong2*>(wsumu + (c2 << 5) + (ph << 4));
        #pragma unroll
        for (int q = 0; q < 8; ++q) {
            ulonglong2 w = wq[q];
            fma2(accA[2*q  ], w.x, x0); fma2(accB[2*q  ], w.x, x1);
            fma2(accA[2*q+1], w.y, x0); fma2(accB[2*q+1], w.y, x1);
        }
    }

    // ---- main loop: acc += (-w)[r][c2][o] (.) xr-pair (xr float2 used directly) ----
    const u64* wsu = reinterpret_cast<const u64*>(ws);
    #pragma unroll 1
    for (int r = 0; r < NSEL; ++r) {
        const int a0 = b0 + (int)selp[r*NTHR + pp]       - 512;
        const int a1 = b1 + (int)selp[r*NTHR + pp + 128] - 512;
        #pragma unroll
        for (int c2 = 0; c2 < NC2; ++c2) {
            const u64 v0 = xs2u[c2*CPLANE + a0];
            const u64 v1 = xs2u[c2*CPLANE + a1];
            const ulonglong2* wq = reinterpret_cast<const ulonglong2*>(
                wsu + ((r*8 + c2) << 5) + (ph << 4));
            #pragma unroll
            for (int q = 0; q < 8; ++q) {
                ulonglong2 w = wq[q];
                fma2(accA[2*q  ], w.x, v0); fma2(accB[2*q  ], w.x, v1);
                fma2(accA[2*q+1], w.y, v0); fma2(accB[2*q+1], w.y, v1);
            }
        }
    }

    // ---- epilogue: out = bias + acc.x + acc.y ; store 16 o x 2 pixels ----
    const int gx = gx0 + px;
    const int gy_a = gy0 + py;
    const int gy_b = gy_a + 4;
    float* ob = out + (size_t)bz*OUTC*HW + (size_t)(ph*16)*HW + gx;
    #pragma unroll
    for (int o = 0; o < 16; ++o) {
        const float bias = cbs[ph*16 + o];
        float2 va = unpack2(accA[o]);
        float2 vb = unpack2(accB[o]);
        ob[o*HW + gy_a*WWIDTH] = bias + (va.x + va.y);
        ob[o*HW + gy_b*WWIDTH] = bias + (vb.x + vb.y);
    }
}

extern "C" void kernel_launch(void* const* d_in, const int* in_sizes, int n_in,
                              void* d_out, int out_size)
{
    const float* x  = (const float*)d_in[0];
    const float* cw = (const float*)d_in[1];
    const float* cb = (const float*)d_in[2];
    float* out = (float*)d_out;

    cudaFuncSetAttribute(pkc2d_kernel,
                         cudaFuncAttributeMaxDynamicSharedMemorySize, SMEM_BYTES);

    dim3 block(TW, TH, 1);
    dim3 grid(WWIDTH/TW, HH/TH, B_);
    pkc2d_kernel<<<grid, block, SMEM_BYTES>>>(x, cw, cb, out);
}